// round 17
// baseline (speedup 1.0000x reference)
#include <cuda_runtime.h>
#include <math.h>

// Problem constants (fixed by reference: IMG=2048, strides 8/16/32, B=2, M=128)
#define L3 65536
#define L4 16384
#define L5 4096
#define LTOT (L3 + L4 + L5)   // 86016
#define NB 2
#define NGT 128

__device__ __forceinline__ float fdiv_approx(float a, float b) {
    float r;
    asm("div.approx.f32 %0, %1, %2;" : "=f"(r) : "f"(a), "f"(b));
    return r;
}
__device__ __forceinline__ float fsqrt_approx(float a) {
    float r;
    asm("sqrt.approx.f32 %0, %1;" : "=f"(r) : "f"(a));
    return r;
}

// Fused kernel: 1344 blocks x 128 threads, 1 location/thread (128 locs/block).
// Each block is (batch, level)-uniform (boundaries % 128 == 0). Block spans:
// p3 = half a row (x-band prune), p4 = 1 row, p5 = 2 rows.
// Pre-barrier critical path contains ONLY the gt load -> candidate test ->
// ballot -> STS (pred-dependent work moved after the scan so in-order issue
// never stalls the barrier on the pred LDG). Argmax key = raw fp32 bits of
// mm (u32), recomputed inline; strict '>' + ascending-j scan order gives
// jnp.argmax first-index ties. Warp-local coalesced float4 output copy.
__global__ __launch_bounds__(128) void fcos_fused(
    const float* __restrict__ gt,      // (B, 128, 5)
    const float* __restrict__ p3,      // (B, L3, 4)
    const float* __restrict__ p4,
    const float* __restrict__ p5,
    float* __restrict__ out)           // (B, LTOT, 9)
{
    __shared__ float4 sbox[NGT];                 // compacted candidate boxes
    __shared__ int swc[4];                       // per-warp shortlist count
    __shared__ float sOut[128 * 9];              // staged output (4608 B)

    const int tid   = threadIdx.x;               // 0..127
    const int w     = tid >> 5;
    const int lane  = tid & 31;
    const int gbase = blockIdx.x * 128;
    const int b     = (gbase >= LTOT) ? 1 : 0;
    const int locb  = gbase - b * LTOT;

    // Level selection — uniform per block.
    float s, lo, hi;
    const float* pred;
    int nshift, off;
    if (locb < L3) {
        s = 8.0f;  lo = 0.0f;   hi = 64.0f;
        pred = p3 + (size_t)b * L3 * 4; nshift = 8; off = 0;          // n=256
    } else if (locb < L3 + L4) {
        s = 16.0f; lo = 64.0f;  hi = 128.0f;
        pred = p4 + (size_t)b * L4 * 4; nshift = 7; off = L3;         // n=128
    } else {
        s = 32.0f; lo = 128.0f; hi = INFINITY;
        pred = p5 + (size_t)b * L5 * 4; nshift = 6; off = L3 + L4;    // n=64
    }
    const int nmask = (1 << nshift) - 1;

    const int l0   = locb - off;             // level-local block start
    const int lidx = l0 + tid;               // this thread's location
    const int row  = lidx >> nshift;
    const int col  = lidx & nmask;
    // Analytic coords: (k+0.5)*2^m exact in fp32 -> bitwise equal to ref.
    const float y = ((float)row + 0.5f) * s;
    const float x = ((float)col + 0.5f) * s;

    // Block bands. Rows r0..r1; if single-row block (p3), tight x-band too.
    const int r0 = l0 >> nshift, r1 = (l0 + 127) >> nshift;
    const float ylo = ((float)r0 + 0.5f) * s;
    const float yhi = ((float)r1 + 0.5f) * s;
    float xblo, xbhi;
    if (r0 == r1) {
        xblo = ((float)(l0 & nmask) + 0.5f) * s;
        xbhi = xblo + 127.0f * s;
    } else {
        xblo = -1e30f; xbhi = 1e30f;
    }

    // gt load issued first (phase 1 consumes it; this is THE critical load).
    const float* g = gt + ((size_t)(b * NGT + tid)) * 5;
    const float bx0 = g[0], by0 = g[1], bx1 = g[2], by1 = g[3];

    // Prediction (LDG.128) issued here but consumed only AFTER the scan, so
    // its latency never blocks the pre-barrier chain (in-order issue).
    const float4 p = reinterpret_cast<const float4*>(pred)[lidx];

    // ---- Phase 1: 4 warps build compacted per-warp shortlists ----
    {
        // Valid-center window: x in (max(x0,x1-hi), min(x1,x0+hi)), same in y.
        const float xl = fmaxf(bx0, bx1 - hi), xh = fminf(bx1, bx0 + hi);
        const float yl = fmaxf(by0, by1 - hi), yh = fminf(by1, by0 + hi);
        const bool cand = (xh > xl) && (yh > ylo) && (yl < yhi) &&
                          (xl < xbhi) && (xh > xblo);
        const unsigned mask = __ballot_sync(0xFFFFFFFFu, cand);
        if (cand) {
            const int slot = (w << 5) + __popc(mask & ((1u << lane) - 1u));
            sbox[slot] = make_float4(bx0, by0, bx1, by1);
        }
        if (lane == 0) swc[w] = __popc(mask);
    }
    __syncthreads();

    // ---- Phase 2: dense scan; u32 key = fp32 bits of mm, inline ----
    unsigned best = 0u;     // 0 = no match (valid mm bits ~0x4CBE... > 0)
    int bslot = 0;
    #pragma unroll
    for (int ws = 0; ws < 4; ++ws) {
        const int cnt  = swc[ws];
        const int base = ws << 5;
        for (int k = 0; k < cnt; ++k) {
            const float4 bx = sbox[base + k];
            const float l  = x - bx.x;
            const float t  = y - bx.y;
            const float r  = bx.z - x;
            const float bt = bx.w - y;
            const float pmin = fminf(fminf(l, t), fminf(r, bt));
            const float pmax = fmaxf(fmaxf(l, t), fmaxf(r, bt));
            // Same fp32 rounding as reference: (x1-x0)*(y1-y0) then subtract.
            const float mmv = 1e8f - (bx.z - bx.x) * (bx.w - bx.y);
            const unsigned key = __float_as_uint(mmv);
            if (pmin > 0.0f && pmax > lo && pmax < hi && key > best) {
                best = key; bslot = base + k;
            }
        }
    }

    // ---- Phase 3: stage all 9 outputs (match + decode) ----
    {
        const float inv_s = 1.0f / s;
        float* o = sOut + tid * 9;
        if (best == 0u) {
            o[0] = o[1] = o[2] = o[3] = -1.0f;
            o[4] = -1.0f;
        } else {
            const float4 bx = sbox[bslot];
            const float d0 = (x - bx.x) * inv_s;
            const float d1 = (y - bx.y) * inv_s;
            const float d2 = (bx.z - x) * inv_s;
            const float d3 = (bx.w - y) * inv_s;
            const float lrmin = fminf(d0, d2), lrmax = fmaxf(d0, d2);
            const float tbmin = fminf(d1, d3), tbmax = fmaxf(d1, d3);
            const float ratio = fdiv_approx(fminf(lrmin, tbmin),
                                            fmaxf(lrmax, tbmax) + 1e-6f);
            o[0] = d0; o[1] = d1; o[2] = d2; o[3] = d3;
            o[4] = fsqrt_approx(fmaxf(ratio, 0.0f));
        }
        // Decode half — pred load has long since landed.
        o[5] = fmaxf(x - fmaxf(p.x, 0.0f) * s, 0.0f);
        o[6] = fmaxf(y - fmaxf(p.y, 0.0f) * s, 0.0f);
        o[7] = fmaxf(x + fmaxf(p.z, 0.0f) * s, 0.0f);
        o[8] = fmaxf(y + fmaxf(p.w, 0.0f) * s, 0.0f);
    }
    __syncwarp();   // warp-local: each warp copies only its own staged region

    // ---- Phase 4: per-warp coalesced copy of its own 288-float region ----
    // Warp region: sOut[288w .. 288(w+1)) = 72 float4 -> contiguous output.
    {
        const float4* src = reinterpret_cast<const float4*>(sOut + 288 * w);
        float4* dst = reinterpret_cast<float4*>(
            out + ((size_t)b * LTOT + off + l0) * 9 + 288 * w);
        #pragma unroll
        for (int k = 0; k < 2; ++k)
            dst[k * 32 + lane] = src[k * 32 + lane];
        if (lane < 8)
            dst[64 + lane] = src[64 + lane];
    }
}

extern "C" void kernel_launch(void* const* d_in, const int* in_sizes, int n_in,
                              void* d_out, int out_size) {
    const float* gt = (const float*)d_in[3];
    const float* p3 = (const float*)d_in[4];
    const float* p4 = (const float*)d_in[5];
    const float* p5 = (const float*)d_in[6];
    float* out = (float*)d_out;

    const int blocks = NB * LTOT / 128;   // 1344
    fcos_fused<<<blocks, 128>>>(gt, p3, p4, p5, out);
}